// round 15
// baseline (speedup 1.0000x reference)
#include <cuda_runtime.h>
#include <cuda_fp16.h>
#include <stdint.h>
#include <math.h>

#define S_LEN 4096
#define D_MODEL 320
#define DU32 160          // D_MODEL halves as u32 (== float2 per row)
#define NH 8
#define DH 40
#define BR 128            // q rows per CTA (4 warps x m32)
#define BC 64
#define NSPLIT 2
#define KRANGE (S_LEN / NSPLIT)
#define LOG2E 1.4426950408889634f

// -------- scratch (device globals: allocation-free) --------
__device__ __align__(16) __half g_wh[4 * D_MODEL * D_MODEL];
__device__ __align__(16) __half g_qh[S_LEN * D_MODEL];
__device__ __align__(16) __half g_kh[S_LEN * D_MODEL];
__device__ __align__(16) __half g_vh[S_LEN * D_MODEL];
__device__ __align__(16) __half g_ch[S_LEN * D_MODEL];
__device__ __align__(16) __half g_cl[S_LEN * D_MODEL];
__device__ float  g_po[NSPLIT][S_LEN * D_MODEL];   // unnormalized O partials
__device__ float  g_pl[NSPLIT][NH * S_LEN];        // l partials

// ============================================================
// weight conversion: fp32 -> fp16 (scale folded into Wq)
// ============================================================
__global__ void __launch_bounds__(256) convert_w_kernel(
    const float* __restrict__ Wq, const float* __restrict__ Wk,
    const float* __restrict__ Wv, const float* __restrict__ Wo)
{
    int z = blockIdx.z;
    const float* W = (z == 0) ? Wq : (z == 1) ? Wk : (z == 2) ? Wv : Wo;
    float scale = (z == 0) ? rsqrtf((float)DH) * LOG2E : 1.0f;
    int i = blockIdx.x * 256 + threadIdx.x;
    if (i < D_MODEL * D_MODEL) {
        float v = W[i] * scale;
        g_wh[z * D_MODEL * D_MODEL + i] = __float2half_rn(v);
    }
}

// ============================================================
// HMMA / async helpers
// ============================================================
__device__ __forceinline__ void mma_f16(float c[4], uint32_t a0, uint32_t a1,
                                        uint32_t a2, uint32_t a3,
                                        uint32_t b0, uint32_t b1)
{
    asm volatile(
        "mma.sync.aligned.m16n8k16.row.col.f32.f16.f16.f32 "
        "{%0,%1,%2,%3}, {%4,%5,%6,%7}, {%8,%9}, {%0,%1,%2,%3};\n"
        : "+f"(c[0]), "+f"(c[1]), "+f"(c[2]), "+f"(c[3])
        : "r"(a0), "r"(a1), "r"(a2), "r"(a3), "r"(b0), "r"(b1));
}

__device__ __forceinline__ void mma_f16_k8(float c[4], uint32_t a0, uint32_t a1,
                                           uint32_t b0)
{
    asm volatile(
        "mma.sync.aligned.m16n8k8.row.col.f32.f16.f16.f32 "
        "{%0,%1,%2,%3}, {%4,%5}, {%6}, {%0,%1,%2,%3};\n"
        : "+f"(c[0]), "+f"(c[1]), "+f"(c[2]), "+f"(c[3])
        : "r"(a0), "r"(a1), "r"(b0));
}

__device__ __forceinline__ void ldmatrix_x4(uint32_t& r0, uint32_t& r1,
                                            uint32_t& r2, uint32_t& r3, uint32_t addr)
{
    asm volatile("ldmatrix.sync.aligned.m8n8.x4.shared.b16 {%0,%1,%2,%3}, [%4];"
                 : "=r"(r0), "=r"(r1), "=r"(r2), "=r"(r3) : "r"(addr));
}

__device__ __forceinline__ void ldmatrix_x2(uint32_t& r0, uint32_t& r1, uint32_t addr)
{
    asm volatile("ldmatrix.sync.aligned.m8n8.x2.shared.b16 {%0,%1}, [%2];"
                 : "=r"(r0), "=r"(r1) : "r"(addr));
}

__device__ __forceinline__ void ldmatrix_x4_trans(uint32_t& r0, uint32_t& r1,
                                                  uint32_t& r2, uint32_t& r3, uint32_t addr)
{
    asm volatile("ldmatrix.sync.aligned.m8n8.x4.trans.shared.b16 {%0,%1,%2,%3}, [%4];"
                 : "=r"(r0), "=r"(r1), "=r"(r2), "=r"(r3) : "r"(addr));
}

__device__ __forceinline__ uint32_t exp2_f16x2(float s0, float s1)
{
    __half2 h = __floats2half2_rn(s0, s1);
    uint32_t r;
    asm volatile("ex2.approx.f16x2 %0, %1;" : "=r"(r) : "r"(*(uint32_t*)&h));
    return r;
}

#define CP_ASYNC16(dst, src) \
    asm volatile("cp.async.cg.shared.global [%0], [%1], 16;\n" :: "r"(dst), "l"(src))
#define CP_COMMIT() asm volatile("cp.async.commit_group;\n" ::: "memory")
#define CP_WAIT1() asm volatile("cp.async.wait_group 1;\n" ::: "memory")
#define CP_WAIT0() asm volatile("cp.async.wait_group 0;\n" ::: "memory")

// ============================================================
// 2-term split-fp16 HMMA GEMM: C = A @ W^T. (unchanged R14)
// ============================================================
#define PA_STR 12
#define GSTAGE_B (64 * PA_STR * 4)   // bytes per smem stage

__global__ void __launch_bounds__(128) gemm_qkv_h(const float* __restrict__ x)
{
    __shared__ __align__(16) uint32_t Ah[2][64 * PA_STR];
    __shared__ __align__(16) uint32_t Al[2][64 * PA_STR];
    __shared__ __align__(16) uint32_t Wh[2][64 * PA_STR];

    const int z = blockIdx.z;
    const float2* __restrict__ x2 = (const float2*)x;
    const uint32_t* __restrict__ wh32 = (const uint32_t*)(g_wh + z * D_MODEL * D_MODEL);
    uint32_t* __restrict__ out32 =
        (uint32_t*)((z == 0) ? g_qh : (z == 1) ? g_kh : g_vh);

    const int tid = threadIdx.x;
    const int w = tid >> 5;
    const int lane = tid & 31;
    const int g = lane >> 2;
    const int t = lane & 3;
    const int m0 = blockIdx.x * 64;
    const int n0 = blockIdx.y * 64;
    const int rr = tid >> 3;
    const int cc = tid & 7;

    const int quad = lane >> 3;
    const int qi = lane & 7;
    const uint32_t ah_sh = (uint32_t)__cvta_generic_to_shared(&Ah[0][0]);
    const uint32_t al_sh = (uint32_t)__cvta_generic_to_shared(&Al[0][0]);
    const uint32_t wh_sh = (uint32_t)__cvta_generic_to_shared(&Wh[0][0]);
    const uint32_t a_off = (((w * 16 + (quad & 1) * 8 + qi) * PA_STR) + (quad >> 1) * 4) * 4;
    const uint32_t w_off = ((((quad >> 1) * 8 + qi) * PA_STR) + (quad & 1) * 4) * 4;

    float acc[8][4] = {};
    float2 ax[4];
    uint32_t wv[4];

    #pragma unroll
    for (int it = 0; it < 4; it++) {
        int row = rr + it * 16;
        ax[it] = x2[(m0 + row) * DU32 + cc];
        wv[it] = wh32[(n0 + row) * DU32 + cc];
    }

    for (int kb = 0; kb < 20; kb++) {
        const int s = kb & 1;
        #pragma unroll
        for (int it = 0; it < 4; it++) {
            int row = rr + it * 16;
            float2 v = ax[it];
            __half2 h = __floats2half2_rn(v.x, v.y);
            __half2 l = __floats2half2_rn(v.x - __half2float(__low2half(h)),
                                          v.y - __half2float(__high2half(h)));
            Ah[s][row * PA_STR + cc] = *(uint32_t*)&h;
            Al[s][row * PA_STR + cc] = *(uint32_t*)&l;
            Wh[s][row * PA_STR + cc] = wv[it];
        }
        __syncthreads();

        if (kb < 19) {
            #pragma unroll
            for (int it = 0; it < 4; it++) {
                int row = rr + it * 16;
                ax[it] = x2[(m0 + row) * DU32 + (kb + 1) * 8 + cc];
                wv[it] = wh32[(n0 + row) * DU32 + (kb + 1) * 8 + cc];
            }
        }

        const uint32_t sb = s * GSTAGE_B;
        uint32_t a0, a1, a2, a3, l0, l1, l2, l3;
        ldmatrix_x4(a0, a1, a2, a3, ah_sh + sb + a_off);
        ldmatrix_x4(l0, l1, l2, l3, al_sh + sb + a_off);

        #pragma unroll
        for (int ap = 0; ap < 4; ap++) {
            uint32_t b0, b1, b2, b3;
            ldmatrix_x4(b0, b1, b2, b3, wh_sh + sb + w_off + ap * (16 * PA_STR * 4));
            mma_f16(acc[2 * ap],     a0, a1, a2, a3, b0, b1);
            mma_f16(acc[2 * ap],     l0, l1, l2, l3, b0, b1);
            mma_f16(acc[2 * ap + 1], a0, a1, a2, a3, b2, b3);
            mma_f16(acc[2 * ap + 1], l0, l1, l2, l3, b2, b3);
        }
    }

    int row = m0 + w * 16 + g;
    #pragma unroll
    for (int a = 0; a < 8; a++) {
        int colu = (n0 >> 1) + 4 * a + t;
        __half2 v0 = __floats2half2_rn(acc[a][0], acc[a][1]);
        __half2 v1 = __floats2half2_rn(acc[a][2], acc[a][3]);
        out32[row * DU32 + colu] = *(uint32_t*)&v0;
        out32[(row + 8) * DU32 + colu] = *(uint32_t*)&v1;
    }
}

__global__ void __launch_bounds__(128) gemm_out_h(
    const float* __restrict__ bo, float* __restrict__ out)
{
    __shared__ __align__(16) uint32_t Ah[2][64 * PA_STR];
    __shared__ __align__(16) uint32_t Al[2][64 * PA_STR];
    __shared__ __align__(16) uint32_t Wh[2][64 * PA_STR];

    const uint32_t* __restrict__ xh32 = (const uint32_t*)g_ch;
    const uint32_t* __restrict__ xl32 = (const uint32_t*)g_cl;
    const uint32_t* __restrict__ wh32 = (const uint32_t*)(g_wh + 3 * D_MODEL * D_MODEL);

    const int tid = threadIdx.x;
    const int w = tid >> 5;
    const int lane = tid & 31;
    const int g = lane >> 2;
    const int t = lane & 3;
    const int m0 = blockIdx.x * 64;
    const int n0 = blockIdx.y * 64;
    const int rr = tid >> 3;
    const int cc = tid & 7;

    const int quad = lane >> 3;
    const int qi = lane & 7;
    const uint32_t ah_sh = (uint32_t)__cvta_generic_to_shared(&Ah[0][0]);
    const uint32_t al_sh = (uint32_t)__cvta_generic_to_shared(&Al[0][0]);
    const uint32_t wh_sh = (uint32_t)__cvta_generic_to_shared(&Wh[0][0]);
    const uint32_t a_off = (((w * 16 + (quad & 1) * 8 + qi) * PA_STR) + (quad >> 1) * 4) * 4;
    const uint32_t w_off = ((((quad >> 1) * 8 + qi) * PA_STR) + (quad & 1) * 4) * 4;

    float acc[8][4] = {};
    uint32_t av[4], lv[4], wv[4];

    #pragma unroll
    for (int it = 0; it < 4; it++) {
        int row = rr + it * 16;
        av[it] = xh32[(m0 + row) * DU32 + cc];
        lv[it] = xl32[(m0 + row) * DU32 + cc];
        wv[it] = wh32[(n0 + row) * DU32 + cc];
    }

    for (int kb = 0; kb < 20; kb++) {
        const int s = kb & 1;
        #pragma unroll
        for (int it = 0; it < 4; it++) {
            int row = rr + it * 16;
            Ah[s][row * PA_STR + cc] = av[it];
            Al[s][row * PA_STR + cc] = lv[it];
            Wh[s][row * PA_STR + cc] = wv[it];
        }
        __syncthreads();

        if (kb < 19) {
            #pragma unroll
            for (int it = 0; it < 4; it++) {
                int row = rr + it * 16;
                av[it] = xh32[(m0 + row) * DU32 + (kb + 1) * 8 + cc];
                lv[it] = xl32[(m0 + row) * DU32 + (kb + 1) * 8 + cc];
                wv[it] = wh32[(n0 + row) * DU32 + (kb + 1) * 8 + cc];
            }
        }

        const uint32_t sb = s * GSTAGE_B;
        uint32_t a0, a1, a2, a3, l0, l1, l2, l3;
        ldmatrix_x4(a0, a1, a2, a3, ah_sh + sb + a_off);
        ldmatrix_x4(l0, l1, l2, l3, al_sh + sb + a_off);

        #pragma unroll
        for (int ap = 0; ap < 4; ap++) {
            uint32_t b0, b1, b2, b3;
            ldmatrix_x4(b0, b1, b2, b3, wh_sh + sb + w_off + ap * (16 * PA_STR * 4));
            mma_f16(acc[2 * ap],     a0, a1, a2, a3, b0, b1);
            mma_f16(acc[2 * ap],     l0, l1, l2, l3, b0, b1);
            mma_f16(acc[2 * ap + 1], a0, a1, a2, a3, b2, b3);
            mma_f16(acc[2 * ap + 1], l0, l1, l2, l3, b2, b3);
        }
    }

    int row = m0 + w * 16 + g;
    #pragma unroll
    for (int a = 0; a < 8; a++) {
        int col = n0 + 8 * a + 2 * t;
        float b0v = bo[col], b1v = bo[col + 1];
        float2 v0 = make_float2(acc[a][0] + b0v, acc[a][1] + b1v);
        float2 v1 = make_float2(acc[a][2] + b0v, acc[a][3] + b1v);
        *(float2*)&out[row * D_MODEL + col] = v0;
        *(float2*)&out[(row + 8) * D_MODEL + col] = v1;
    }
}

// ============================================================
// Flash attention, split-K x2. CTA = 128 q x 1 head x 2048 keys.
// Exact K=40 QK: 2 x k16 + 1 x m16n8k8 (no padding). Q/K tiles
// 20 u32 wide (stride 20, conflict-free). V keeps stride 28 with
// the ones-column for l. 2-stage cp.async, register P.
// ============================================================
#define QS_STR 20
#define KS_STR 20
#define VS_STR 28
#define K_TILE (64 * KS_STR)
#define K_TILE_B (K_TILE * 4)
#define V_TILE (64 * VS_STR)
#define V_TILE_B (V_TILE * 4)

__global__ void __launch_bounds__(128, 4) attn_kernel()
{
    __shared__ __align__(16) uint32_t Qs[128 * QS_STR];
    __shared__ __align__(16) uint32_t Ks[2 * K_TILE];
    __shared__ __align__(16) uint32_t Vs[2 * V_TILE];

    const uint32_t* __restrict__ q32 = (const uint32_t*)g_qh;
    const uint32_t* __restrict__ k32 = (const uint32_t*)g_kh;
    const uint32_t* __restrict__ v32 = (const uint32_t*)g_vh;

    const int tid = threadIdx.x;
    const int w = tid >> 5;
    const int lane = tid & 31;
    const int g = lane >> 2;
    const int t = lane & 3;
    const int head = blockIdx.y;
    const int split = blockIdx.z;
    const int q0 = blockIdx.x * BR;
    const int hoff = head * (DH / 2);
    const int kb0 = split * KRANGE;

    const uint32_t ks_sh = (uint32_t)__cvta_generic_to_shared(&Ks[0]);
    const uint32_t vs_sh = (uint32_t)__cvta_generic_to_shared(&Vs[0]);

    // ---- prologue: V col 20 = ones, 21..23 zero (both stages) ----
    for (int idx = tid; idx < 2 * 64 * 4; idx += 128) {
        int st = idx >> 8;
        int rem = idx & 255;
        int r = rem >> 2, c = 20 + (rem & 3);
        Vs[st * V_TILE + r * VS_STR + c] = (c == 20) ? 0x3C003C00u : 0u;
    }

    // ---- load Q tile: 128 rows x 20 u32 (exact) ----
    for (int idx = tid; idx < 128 * 20; idx += 128) {
        int r = idx / 20, c = idx % 20;
        Qs[r * QS_STR + c] = q32[(q0 + r) * DU32 + hoff + c];
    }

    // ---- hoisted cp.async addressing (K stride 20, V stride 28) ----
    const uint32_t* srcPtr[5];
    uint32_t dstOff[5];
    uint32_t stStep[5];
    #pragma unroll
    for (int j = 0; j < 5; j++) {
        int idx = tid + j * 128;
        int i2 = idx;
        bool isV = i2 >= 320;
        if (isV) i2 -= 320;
        int r = i2 / 5, c = i2 % 5;
        srcPtr[j] = (isV ? v32 : k32) + (kb0 + r) * DU32 + hoff + c * 4;
        dstOff[j] = isV ? (vs_sh + (r * VS_STR + c * 4) * 4)
                        : (ks_sh + (r * KS_STR + c * 4) * 4);
        stStep[j] = isV ? V_TILE_B : K_TILE_B;
    }

    #pragma unroll
    for (int j = 0; j < 5; j++) {
        CP_ASYNC16(dstOff[j], srcPtr[j]);
        srcPtr[j] += BC * DU32;
    }
    CP_COMMIT();
    __syncthreads();

    // ---- Q A-fragments: 2 m-halves x (2 k16 + 1 k8) ----
    uint32_t qa[2][2][4];   // k16 steps
    uint32_t q8[2][2];      // k8 step (u32 col 16+t)
    #pragma unroll
    for (int h = 0; h < 2; h++) {
        int r0 = (w * 32 + h * 16 + g) * QS_STR;
        int r1 = r0 + 8 * QS_STR;
        #pragma unroll
        for (int ks = 0; ks < 2; ks++) {
            qa[h][ks][0] = Qs[r0 + ks * 8 + t];
            qa[h][ks][1] = Qs[r1 + ks * 8 + t];
            qa[h][ks][2] = Qs[r0 + ks * 8 + t + 4];
            qa[h][ks][3] = Qs[r1 + ks * 8 + t + 4];
        }
        q8[h][0] = Qs[r0 + 16 + t];
        q8[h][1] = Qs[r1 + 16 + t];
    }

    // ---- per-lane ldmatrix base addresses ----
    const int kq = lane >> 3;
    const int ki = lane & 7;
    const uint32_t kbase = ks_sh +
        ((((kq >> 1) * 8 + ki) * KS_STR) + (kq & 1) * 4) * 4;
    const uint32_t kbase2 = ks_sh + ((lane & 15) * KS_STR + 16) * 4;   // x2, col 16
    const uint32_t vbase = vs_sh + (lane & 15) * (VS_STR * 4) + (lane >> 4) * 16;

    float o0[6][4] = {};   // m-half 0: atoms 0..4 cols, atom 5 = l
    float o1[6][4] = {};   // m-half 1

    const int NIT = KRANGE / BC;
    for (int iter = 0; iter < NIT; iter++) {
        const int st = iter & 1;

        if (iter + 1 < NIT) {
            #pragma unroll
            for (int j = 0; j < 5; j++) {
                CP_ASYNC16(dstOff[j] + (uint32_t)((iter + 1) & 1) * stStep[j], srcPtr[j]);
                srcPtr[j] += BC * DU32;
            }
            CP_COMMIT();
            CP_WAIT1();
        } else {
            CP_WAIT0();
        }
        __syncthreads();

        const uint32_t kst = kbase + st * K_TILE_B;
        const uint32_t kst2 = kbase2 + st * K_TILE_B;
        const uint32_t vst = vbase + st * V_TILE_B;

        // ---- S = Q K^T per atom-pair (2xk16 + k8); P = 2^S ----
        uint32_t pa01[8], pa23[8];   // P for m-half 0
        uint32_t pb01[8], pb23[8];   // P for m-half 1
        #pragma unroll
        for (int ap = 0; ap < 4; ap++) {
            float sA0[4] = {}, sA1[4] = {}, sB0[4] = {}, sB1[4] = {};
            const uint32_t apo = ap * (16 * KS_STR * 4);
            #pragma unroll
            for (int ks = 0; ks < 2; ks++) {
                uint32_t b0, b1, b2, b3;
                ldmatrix_x4(b0, b1, b2, b3, kst + apo + ks * 32);
                mma_f16(sA0, qa[0][ks][0], qa[0][ks][1], qa[0][ks][2], qa[0][ks][3], b0, b1);
                mma_f16(sA1, qa[1][ks][0], qa[1][ks][1], qa[1][ks][2], qa[1][ks][3], b0, b1);
                mma_f16(sB0, qa[0][ks][0], qa[0][ks][1], qa[0][ks][2], qa[0][ks][3], b2, b3);
                mma_f16(sB1, qa[1][ks][0], qa[1][ks][1], qa[1][ks][2], qa[1][ks][3], b2, b3);
            }
            {
                uint32_t e0, e1;
                ldmatrix_x2(e0, e1, kst2 + apo);
                mma_f16_k8(sA0, q8[0][0], q8[0][1], e0);
                mma_f16_k8(sA1, q8[1][0], q8[1][1], e0);
                mma_f16_k8(sB0, q8[0][0], q8[0][1], e1);
                mma_f16_k8(sB1, q8[1][0], q8[1][1], e1);
            }
            int a0i = 2 * ap, a1i = 2 * ap + 1;
            pa01[a0i] = exp2_f16x2(sA0[0], sA0[1]);
            pa23[a0i] = exp2_f16x2(sA0[2], sA0[3]);
            pb01[a0i] = exp2_f16x2(sA1[0], sA1[1]);
            pb23[a0i] = exp2_f16x2(sA1[2], sA1[3]);
            pa01[a1i] = exp2_f16x2(sB0[0], sB0[1]);
            pa23[a1i] = exp2_f16x2(sB0[2], sB0[3]);
            pb01[a1i] = exp2_f16x2(sB1[0], sB1[1]);
            pb23[a1i] = exp2_f16x2(sB1[2], sB1[3]);
        }

        // ---- O += P @ [V | 1]: x4.trans loads 2 n-atoms per instr ----
        #pragma unroll
        for (int ks = 0; ks < 4; ks++) {
            uint32_t vk = vst + ks * (16 * VS_STR * 4);
            uint32_t a0 = pa01[2 * ks], a1 = pa23[2 * ks];
            uint32_t a2 = pa01[2 * ks + 1], a3 = pa23[2 * ks + 1];
            uint32_t c0 = pb01[2 * ks], c1 = pb23[2 * ks];
            uint32_t c2 = pb01[2 * ks + 1], c3 = pb23[2 * ks + 1];
            #pragma unroll
            for (int np = 0; np < 3; np++) {
                uint32_t b0, b1, b2, b3;
                ldmatrix_x4_trans(b0, b1, b2, b3, vk + np * 32);
                mma_f16(o0[2 * np],     a0, a1, a2, a3, b0, b1);
                mma_f16(o1[2 * np],     c0, c1, c2, c3, b0, b1);
                mma_f16(o0[2 * np + 1], a0, a1, a2, a3, b2, b3);
                mma_f16(o1[2 * np + 1], c0, c1, c2, c3, b2, b3);
            }
        }
        __syncthreads();
    }

    // ---- epilogue: store unnormalized partials, both halves ----
    float* po = &g_po[split][0];
    #pragma unroll
    for (int h = 0; h < 2; h++) {
        float (*o)[4] = (h == 0) ? o0 : o1;
        int r0 = q0 + w * 32 + h * 16 + g;
        #pragma unroll
        for (int n = 0; n < 5; n++) {
            int col = head * DH + n * 8 + 2 * t;
            *(float2*)&po[r0 * D_MODEL + col] = make_float2(o[n][0], o[n][1]);
            *(float2*)&po[(r0 + 8) * D_MODEL + col] = make_float2(o[n][2], o[n][3]);
        }
        if (t == 0) {
            g_pl[split][head * S_LEN + r0] = o[5][0];
            g_pl[split][head * S_LEN + r0 + 8] = o[5][2];
        }
    }
}

// ============================================================
// Combine (vectorized): ctx = (sum O_s)/(sum l_s) -> (hi,lo) fp16
// ============================================================
__global__ void __launch_bounds__(256) attn_combine()
{
    int j = blockIdx.x * 256 + threadIdx.x;   // pair index over [S_LEN][DU32/2]
    if (j >= S_LEN * (DU32 / 2)) return;
    int row = j / (DU32 / 2);
    int cup = j % (DU32 / 2);
    int head = cup / (DH / 4);   // 10 pairs per head

    float l = 0.f, v0 = 0.f, v1 = 0.f, v2 = 0.f, v3 = 0.f;
    #pragma unroll
    for (int s = 0; s < NSPLIT; s++) {
        l += g_pl[s][head * S_LEN + row];
        float4 a = *(const float4*)&g_po[s][j * 4];
        v0 += a.x; v1 += a.y; v2 += a.z; v3 += a.w;
    }
    float inv = 1.f / l;
    v0 *= inv; v1 *= inv; v2 *= inv; v3 *= inv;

    __half2 h0 = __floats2half2_rn(v0, v1);
    __half2 h1 = __floats2half2_rn(v2, v3);
    __half2 e0 = __floats2half2_rn(v0 - __half2float(__low2half(h0)),
                                   v1 - __half2float(__high2half(h0)));
    __half2 e1 = __floats2half2_rn(v2 - __half2float(__low2half(h1)),
                                   v3 - __half2float(__high2half(h1)));
    ((uint2*)g_ch)[j] = make_uint2(*(uint32_t*)&h0, *(uint32_t*)&h1);
    ((uint2*)g_cl)[j] = make_uint2(*(uint32_t*)&e0, *(uint32_t*)&e1);
}

// ============================================================
extern "C" void kernel_launch(void* const* d_in, const int* in_sizes, int n_in,
                              void* d_out, int out_size)
{
    const float* x  = (const float*)d_in[0];
    const float* Wq = (const float*)d_in[1];
    const float* Wk = (const float*)d_in[2];
    const float* Wv = (const float*)d_in[3];
    const float* Wo = (const float*)d_in[4];
    const float* bo = (const float*)d_in[5];
    float* out = (float*)d_out;

    convert_w_kernel<<<dim3((D_MODEL * D_MODEL + 255) / 256, 1, 4), 256>>>(Wq, Wk, Wv, Wo);

    gemm_qkv_h<<<dim3(S_LEN / 64, D_MODEL / 64, 3), 128>>>(x);
    attn_kernel<<<dim3(S_LEN / BR, NH, NSPLIT), 128>>>();
    attn_combine<<<(S_LEN * (DU32 / 2) + 255) / 256, 256>>>();
    gemm_out_h<<<dim3(S_LEN / 64, D_MODEL / 64), 128>>>(bo, out);
}

// round 16
// speedup vs baseline: 1.1174x; 1.1174x over previous
#include <cuda_runtime.h>
#include <cuda_fp16.h>
#include <stdint.h>
#include <math.h>

#define S_LEN 4096
#define D_MODEL 320
#define DU32 160          // D_MODEL halves as u32 (== float2 per row)
#define NH 8
#define DH 40
#define BR 128            // q rows per CTA (4 warps x m32)
#define BC 64
#define NSPLIT 4
#define KRANGE (S_LEN / NSPLIT)
#define LOG2E 1.4426950408889634f

// -------- scratch (device globals: allocation-free) --------
__device__ __align__(16) __half g_wh[4 * D_MODEL * D_MODEL];
__device__ __align__(16) __half g_qh[S_LEN * D_MODEL];
__device__ __align__(16) __half g_kh[S_LEN * D_MODEL];
__device__ __align__(16) __half g_vh[S_LEN * D_MODEL];
__device__ __align__(16) __half g_ch[S_LEN * D_MODEL];
__device__ __align__(16) __half g_cl[S_LEN * D_MODEL];
__device__ float  g_po[NSPLIT][S_LEN * D_MODEL];   // unnormalized O partials
__device__ float  g_pl[NSPLIT][NH * S_LEN];        // l partials

// ============================================================
// weight conversion: fp32 -> fp16 (scale folded into Wq)
// ============================================================
__global__ void __launch_bounds__(256) convert_w_kernel(
    const float* __restrict__ Wq, const float* __restrict__ Wk,
    const float* __restrict__ Wv, const float* __restrict__ Wo)
{
    int z = blockIdx.z;
    const float* W = (z == 0) ? Wq : (z == 1) ? Wk : (z == 2) ? Wv : Wo;
    float scale = (z == 0) ? rsqrtf((float)DH) * LOG2E : 1.0f;
    int i = blockIdx.x * 256 + threadIdx.x;
    if (i < D_MODEL * D_MODEL) {
        float v = W[i] * scale;
        g_wh[z * D_MODEL * D_MODEL + i] = __float2half_rn(v);
    }
}

// ============================================================
// HMMA / async helpers
// ============================================================
__device__ __forceinline__ void mma_f16(float c[4], uint32_t a0, uint32_t a1,
                                        uint32_t a2, uint32_t a3,
                                        uint32_t b0, uint32_t b1)
{
    asm volatile(
        "mma.sync.aligned.m16n8k16.row.col.f32.f16.f16.f32 "
        "{%0,%1,%2,%3}, {%4,%5,%6,%7}, {%8,%9}, {%0,%1,%2,%3};\n"
        : "+f"(c[0]), "+f"(c[1]), "+f"(c[2]), "+f"(c[3])
        : "r"(a0), "r"(a1), "r"(a2), "r"(a3), "r"(b0), "r"(b1));
}

__device__ __forceinline__ void ldmatrix_x4(uint32_t& r0, uint32_t& r1,
                                            uint32_t& r2, uint32_t& r3, uint32_t addr)
{
    asm volatile("ldmatrix.sync.aligned.m8n8.x4.shared.b16 {%0,%1,%2,%3}, [%4];"
                 : "=r"(r0), "=r"(r1), "=r"(r2), "=r"(r3) : "r"(addr));
}

__device__ __forceinline__ void ldmatrix_x4_trans(uint32_t& r0, uint32_t& r1,
                                                  uint32_t& r2, uint32_t& r3, uint32_t addr)
{
    asm volatile("ldmatrix.sync.aligned.m8n8.x4.trans.shared.b16 {%0,%1,%2,%3}, [%4];"
                 : "=r"(r0), "=r"(r1), "=r"(r2), "=r"(r3) : "r"(addr));
}

__device__ __forceinline__ uint32_t exp2_f16x2(float s0, float s1)
{
    __half2 h = __floats2half2_rn(s0, s1);
    uint32_t r;
    asm volatile("ex2.approx.f16x2 %0, %1;" : "=r"(r) : "r"(*(uint32_t*)&h));
    return r;
}

#define CP_ASYNC16(dst, src) \
    asm volatile("cp.async.cg.shared.global [%0], [%1], 16;\n" :: "r"(dst), "l"(src))
#define CP_COMMIT() asm volatile("cp.async.commit_group;\n" ::: "memory")
#define CP_WAIT1() asm volatile("cp.async.wait_group 1;\n" ::: "memory")
#define CP_WAIT0() asm volatile("cp.async.wait_group 0;\n" ::: "memory")

// ============================================================
// FUSED QKV GEMM: {Q,K,V} = x @ {Wq,Wk,Wv}^T in ONE kernel.
// x tile loaded + hi/lo split ONCE, reused for all 3 outputs.
// 2-term split-fp16, register-prefetch double-buffered smem.
// BM=64 (4 warps x m16), BN=64, k-step 16, 128 threads.
// ============================================================
#define PA_STR 12
#define GTILE (64 * PA_STR)          // u32 per logical tile
#define GSTAGE_B (GTILE * 4)         // bytes per smem stage (single tile)

__global__ void __launch_bounds__(128) gemm_qkv_h(const float* __restrict__ x)
{
    __shared__ __align__(16) uint32_t Ah[2][GTILE];
    __shared__ __align__(16) uint32_t Al[2][GTILE];
    __shared__ __align__(16) uint32_t Wh[2][3][GTILE];

    const float2* __restrict__ x2 = (const float2*)x;
    const uint32_t* __restrict__ w32 = (const uint32_t*)g_wh;

    const int tid = threadIdx.x;
    const int w = tid >> 5;
    const int lane = tid & 31;
    const int g = lane >> 2;
    const int t = lane & 3;
    const int m0 = blockIdx.x * 64;
    const int n0 = blockIdx.y * 64;
    const int rr = tid >> 3;
    const int cc = tid & 7;

    const int quad = lane >> 3;
    const int qi = lane & 7;
    const uint32_t ah_sh = (uint32_t)__cvta_generic_to_shared(&Ah[0][0]);
    const uint32_t al_sh = (uint32_t)__cvta_generic_to_shared(&Al[0][0]);
    const uint32_t wh_sh = (uint32_t)__cvta_generic_to_shared(&Wh[0][0][0]);
    const uint32_t a_off = (((w * 16 + (quad & 1) * 8 + qi) * PA_STR) + (quad >> 1) * 4) * 4;
    const uint32_t w_off = ((((quad >> 1) * 8 + qi) * PA_STR) + (quad & 1) * 4) * 4;

    float acc[3][8][4] = {};
    float2 ax[4];
    uint32_t wv[3][4];

    // preload kb=0
    #pragma unroll
    for (int it = 0; it < 4; it++) {
        int row = rr + it * 16;
        ax[it] = x2[(m0 + row) * DU32 + cc];
        #pragma unroll
        for (int z = 0; z < 3; z++)
            wv[z][it] = w32[z * (D_MODEL * DU32) + (n0 + row) * DU32 + cc];
    }

    for (int kb = 0; kb < 20; kb++) {
        const int s = kb & 1;
        // store stage s
        #pragma unroll
        for (int it = 0; it < 4; it++) {
            int row = rr + it * 16;
            float2 v = ax[it];
            __half2 h = __floats2half2_rn(v.x, v.y);
            __half2 l = __floats2half2_rn(v.x - __half2float(__low2half(h)),
                                          v.y - __half2float(__high2half(h)));
            Ah[s][row * PA_STR + cc] = *(uint32_t*)&h;
            Al[s][row * PA_STR + cc] = *(uint32_t*)&l;
            #pragma unroll
            for (int z = 0; z < 3; z++)
                Wh[s][z][row * PA_STR + cc] = wv[z][it];
        }
        __syncthreads();

        // prefetch kb+1 (overlaps compute)
        if (kb < 19) {
            #pragma unroll
            for (int it = 0; it < 4; it++) {
                int row = rr + it * 16;
                ax[it] = x2[(m0 + row) * DU32 + (kb + 1) * 8 + cc];
                #pragma unroll
                for (int z = 0; z < 3; z++)
                    wv[z][it] = w32[z * (D_MODEL * DU32) + (n0 + row) * DU32 + (kb + 1) * 8 + cc];
            }
        }

        uint32_t a0, a1, a2, a3, l0, l1, l2, l3;
        ldmatrix_x4(a0, a1, a2, a3, ah_sh + s * GSTAGE_B + a_off);
        ldmatrix_x4(l0, l1, l2, l3, al_sh + s * GSTAGE_B + a_off);

        const uint32_t wsb = wh_sh + s * (3 * GSTAGE_B) + w_off;
        #pragma unroll
        for (int z = 0; z < 3; z++) {
            #pragma unroll
            for (int ap = 0; ap < 4; ap++) {
                uint32_t b0, b1, b2, b3;
                ldmatrix_x4(b0, b1, b2, b3,
                            wsb + z * GSTAGE_B + ap * (16 * PA_STR * 4));
                mma_f16(acc[z][2 * ap],     a0, a1, a2, a3, b0, b1);
                mma_f16(acc[z][2 * ap],     l0, l1, l2, l3, b0, b1);
                mma_f16(acc[z][2 * ap + 1], a0, a1, a2, a3, b2, b3);
                mma_f16(acc[z][2 * ap + 1], l0, l1, l2, l3, b2, b3);
            }
        }
    }

    int row = m0 + w * 16 + g;
    #pragma unroll
    for (int z = 0; z < 3; z++) {
        uint32_t* __restrict__ out32 =
            (uint32_t*)((z == 0) ? g_qh : (z == 1) ? g_kh : g_vh);
        #pragma unroll
        for (int a = 0; a < 8; a++) {
            int colu = (n0 >> 1) + 4 * a + t;
            __half2 v0 = __floats2half2_rn(acc[z][a][0], acc[z][a][1]);
            __half2 v1 = __floats2half2_rn(acc[z][a][2], acc[z][a][3]);
            out32[row * DU32 + colu] = *(uint32_t*)&v0;
            out32[(row + 8) * DU32 + colu] = *(uint32_t*)&v1;
        }
    }
}

// ============================================================
// Output projection (unchanged R14)
// ============================================================
__global__ void __launch_bounds__(128) gemm_out_h(
    const float* __restrict__ bo, float* __restrict__ out)
{
    __shared__ __align__(16) uint32_t Ah[2][GTILE];
    __shared__ __align__(16) uint32_t Al[2][GTILE];
    __shared__ __align__(16) uint32_t Wh[2][GTILE];

    const uint32_t* __restrict__ xh32 = (const uint32_t*)g_ch;
    const uint32_t* __restrict__ xl32 = (const uint32_t*)g_cl;
    const uint32_t* __restrict__ wh32 = (const uint32_t*)(g_wh + 3 * D_MODEL * D_MODEL);

    const int tid = threadIdx.x;
    const int w = tid >> 5;
    const int lane = tid & 31;
    const int g = lane >> 2;
    const int t = lane & 3;
    const int m0 = blockIdx.x * 64;
    const int n0 = blockIdx.y * 64;
    const int rr = tid >> 3;
    const int cc = tid & 7;

    const int quad = lane >> 3;
    const int qi = lane & 7;
    const uint32_t ah_sh = (uint32_t)__cvta_generic_to_shared(&Ah[0][0]);
    const uint32_t al_sh = (uint32_t)__cvta_generic_to_shared(&Al[0][0]);
    const uint32_t wh_sh = (uint32_t)__cvta_generic_to_shared(&Wh[0][0]);
    const uint32_t a_off = (((w * 16 + (quad & 1) * 8 + qi) * PA_STR) + (quad >> 1) * 4) * 4;
    const uint32_t w_off = ((((quad >> 1) * 8 + qi) * PA_STR) + (quad & 1) * 4) * 4;

    float acc[8][4] = {};
    uint32_t av[4], lv[4], wv[4];

    #pragma unroll
    for (int it = 0; it < 4; it++) {
        int row = rr + it * 16;
        av[it] = xh32[(m0 + row) * DU32 + cc];
        lv[it] = xl32[(m0 + row) * DU32 + cc];
        wv[it] = wh32[(n0 + row) * DU32 + cc];
    }

    for (int kb = 0; kb < 20; kb++) {
        const int s = kb & 1;
        #pragma unroll
        for (int it = 0; it < 4; it++) {
            int row = rr + it * 16;
            Ah[s][row * PA_STR + cc] = av[it];
            Al[s][row * PA_STR + cc] = lv[it];
            Wh[s][row * PA_STR + cc] = wv[it];
        }
        __syncthreads();

        if (kb < 19) {
            #pragma unroll
            for (int it = 0; it < 4; it++) {
                int row = rr + it * 16;
                av[it] = xh32[(m0 + row) * DU32 + (kb + 1) * 8 + cc];
                lv[it] = xl32[(m0 + row) * DU32 + (kb + 1) * 8 + cc];
                wv[it] = wh32[(n0 + row) * DU32 + (kb + 1) * 8 + cc];
            }
        }

        const uint32_t sb = s * GSTAGE_B;
        uint32_t a0, a1, a2, a3, l0, l1, l2, l3;
        ldmatrix_x4(a0, a1, a2, a3, ah_sh + sb + a_off);
        ldmatrix_x4(l0, l1, l2, l3, al_sh + sb + a_off);

        #pragma unroll
        for (int ap = 0; ap < 4; ap++) {
            uint32_t b0, b1, b2, b3;
            ldmatrix_x4(b0, b1, b2, b3, wh_sh + sb + w_off + ap * (16 * PA_STR * 4));
            mma_f16(acc[2 * ap],     a0, a1, a2, a3, b0, b1);
            mma_f16(acc[2 * ap],     l0, l1, l2, l3, b0, b1);
            mma_f16(acc[2 * ap + 1], a0, a1, a2, a3, b2, b3);
            mma_f16(acc[2 * ap + 1], l0, l1, l2, l3, b2, b3);
        }
    }

    int row = m0 + w * 16 + g;
    #pragma unroll
    for (int a = 0; a < 8; a++) {
        int col = n0 + 8 * a + 2 * t;
        float b0v = bo[col], b1v = bo[col + 1];
        float2 v0 = make_float2(acc[a][0] + b0v, acc[a][1] + b1v);
        float2 v1 = make_float2(acc[a][2] + b0v, acc[a][3] + b1v);
        *(float2*)&out[row * D_MODEL + col] = v0;
        *(float2*)&out[(row + 8) * D_MODEL + col] = v1;
    }
}

// ============================================================
// Flash attention (known-good R14). Split-K x4.
// CTA = 128 q x 1 head x 1024 keys. 4 warps m32 x n64.
// Qs smem, 2-stage cp.async, K via ldmatrix.x4, V via x4.trans,
// fixed-base exp2 softmax, register P, l via ones-column.
// ============================================================
#define QS_STRIDE 28
#define KS_STRIDE 28
#define VS_STRIDE 28
#define KV_TILE (64 * 28)
#define KV_TILE_B (KV_TILE * 4)

__global__ void __launch_bounds__(128, 4) attn_kernel()
{
    __shared__ __align__(16) uint32_t Qs[128 * QS_STRIDE];
    __shared__ __align__(16) uint32_t Ks[2 * KV_TILE];
    __shared__ __align__(16) uint32_t Vs[2 * KV_TILE];

    const uint32_t* __restrict__ q32 = (const uint32_t*)g_qh;
    const uint32_t* __restrict__ k32 = (const uint32_t*)g_kh;
    const uint32_t* __restrict__ v32 = (const uint32_t*)g_vh;

    const int tid = threadIdx.x;
    const int w = tid >> 5;
    const int lane = tid & 31;
    const int g = lane >> 2;
    const int t = lane & 3;
    const int head = blockIdx.y;
    const int split = blockIdx.z;
    const int q0 = blockIdx.x * BR;
    const int hoff = head * (DH / 2);
    const int kb0 = split * KRANGE;

    const uint32_t ks_sh = (uint32_t)__cvta_generic_to_shared(&Ks[0]);
    const uint32_t vs_sh = (uint32_t)__cvta_generic_to_shared(&Vs[0]);

    // ---- prologue: K pad cols zero; V col 20 = ones, 21..23 zero ----
    for (int idx = tid; idx < 2 * 64 * 4; idx += 128) {
        int st = idx >> 8;
        int rem = idx & 255;
        int r = rem >> 2, c = 20 + (rem & 3);
        Ks[st * KV_TILE + r * KS_STRIDE + c] = 0u;
        Vs[st * KV_TILE + r * VS_STRIDE + c] = (c == 20) ? 0x3C003C00u : 0u;
    }

    // ---- load Q tile: 128 rows x 24 u32 ----
    for (int idx = tid; idx < 128 * 24; idx += 128) {
        int r = idx / 24, c = idx % 24;
        Qs[r * QS_STRIDE + c] = (c < 20) ? q32[(q0 + r) * DU32 + hoff + c] : 0u;
    }

    // ---- hoisted cp.async addressing ----
    const uint32_t* srcPtr[5];
    uint32_t dstOff[5];
    #pragma unroll
    for (int j = 0; j < 5; j++) {
        int idx = tid + j * 128;
        int i2 = idx;
        bool isV = i2 >= 320;
        if (isV) i2 -= 320;
        int r = i2 / 5, c = i2 % 5;
        srcPtr[j] = (isV ? v32 : k32) + (kb0 + r) * DU32 + hoff + c * 4;
        dstOff[j] = (isV ? vs_sh : ks_sh) + (r * KS_STRIDE + c * 4) * 4;
    }

    #pragma unroll
    for (int j = 0; j < 5; j++) {
        CP_ASYNC16(dstOff[j], srcPtr[j]);
        srcPtr[j] += BC * DU32;
    }
    CP_COMMIT();
    __syncthreads();

    // ---- Q A-fragments register-resident: 2 m-halves x 3 k-steps ----
    uint32_t qa[2][3][4];
    #pragma unroll
    for (int h = 0; h < 2; h++) {
        int r0 = (w * 32 + h * 16 + g) * QS_STRIDE;
        int r1 = r0 + 8 * QS_STRIDE;
        #pragma unroll
        for (int ks = 0; ks < 3; ks++) {
            qa[h][ks][0] = Qs[r0 + ks * 8 + t];
            qa[h][ks][1] = Qs[r1 + ks * 8 + t];
            qa[h][ks][2] = Qs[r0 + ks * 8 + t + 4];
            qa[h][ks][3] = Qs[r1 + ks * 8 + t + 4];
        }
    }

    // ---- per-lane ldmatrix base addresses ----
    const int kq = lane >> 3;
    const int ki = lane & 7;
    const uint32_t kbase = ks_sh +
        ((((kq >> 1) * 8 + ki) * KS_STRIDE) + (kq & 1) * 4) * 4;
    const uint32_t vbase = vs_sh + (lane & 15) * (VS_STRIDE * 4) + (lane >> 4) * 16;

    float o0[6][4] = {};   // m-half 0: atoms 0..4 cols, atom 5 = l
    float o1[6][4] = {};   // m-half 1

    const int NIT = KRANGE / BC;
    for (int iter = 0; iter < NIT; iter++) {
        const int st = iter & 1;

        if (iter + 1 < NIT) {
            const uint32_t so = ((iter + 1) & 1) * KV_TILE_B;
            #pragma unroll
            for (int j = 0; j < 5; j++) {
                CP_ASYNC16(dstOff[j] + so, srcPtr[j]);
                srcPtr[j] += BC * DU32;
            }
            CP_COMMIT();
            CP_WAIT1();
        } else {
            CP_WAIT0();
        }
        __syncthreads();

        const uint32_t kst = kbase + st * KV_TILE_B;
        const uint32_t vst = vbase + st * KV_TILE_B;

        // ---- S = Q K^T per atom-pair; P = 2^S into registers ----
        uint32_t pa01[8], pa23[8];   // P for m-half 0
        uint32_t pb01[8], pb23[8];   // P for m-half 1
        #pragma unroll
        for (int ap = 0; ap < 4; ap++) {
            float sA0[4] = {}, sA1[4] = {}, sB0[4] = {}, sB1[4] = {};
            #pragma unroll
            for (int ks = 0; ks < 3; ks++) {
                uint32_t b0, b1, b2, b3;
                ldmatrix_x4(b0, b1, b2, b3,
                            kst + ap * (16 * KS_STRIDE * 4) + ks * 32);
                mma_f16(sA0, qa[0][ks][0], qa[0][ks][1], qa[0][ks][2], qa[0][ks][3], b0, b1);
                mma_f16(sA1, qa[1][ks][0], qa[1][ks][1], qa[1][ks][2], qa[1][ks][3], b0, b1);
                mma_f16(sB0, qa[0][ks][0], qa[0][ks][1], qa[0][ks][2], qa[0][ks][3], b2, b3);
                mma_f16(sB1, qa[1][ks][0], qa[1][ks][1], qa[1][ks][2], qa[1][ks][3], b2, b3);
            }
            int a0i = 2 * ap, a1i = 2 * ap + 1;
            pa01[a0i] = exp2_f16x2(sA0[0], sA0[1]);
            pa23[a0i] = exp2_f16x2(sA0[2], sA0[3]);
            pb01[a0i] = exp2_f16x2(sA1[0], sA1[1]);
            pb23[a0i] = exp2_f16x2(sA1[2], sA1[3]);
            pa01[a1i] = exp2_f16x2(sB0[0], sB0[1]);
            pa23[a1i] = exp2_f16x2(sB0[2], sB0[3]);
            pb01[a1i] = exp2_f16x2(sB1[0], sB1[1]);
            pb23[a1i] = exp2_f16x2(sB1[2], sB1[3]);
        }

        // ---- O += P @ [V | 1]: x4.trans loads 2 n-atoms per instr ----
        #pragma unroll
        for (int ks = 0; ks < 4; ks++) {
            uint32_t vk = vst + ks * (16 * VS_STRIDE * 4);
            uint32_t a0 = pa01[2 * ks], a1 = pa23[2 * ks];
            uint32_t a2 = pa01[2 * ks + 1], a3 = pa23[2 * ks + 1];
            uint32_t c0 = pb01[2 * ks], c1 = pb23[2 * ks];
            uint32_t c2 = pb01[2 * ks + 1], c3 = pb23[2 * ks + 1];
            #pragma unroll
            for (int np = 0; np < 3; np++) {
                uint32_t b0, b1, b2, b3;
                ldmatrix_x4_trans(b0, b1, b2, b3, vk + np * 32);
                mma_f16(o0[2 * np],     a0, a1, a2, a3, b0, b1);
                mma_f16(o1[2 * np],     c0, c1, c2, c3, b0, b1);
                mma_f16(o0[2 * np + 1], a0, a1, a2, a3, b2, b3);
                mma_f16(o1[2 * np + 1], c0, c1, c2, c3, b2, b3);
            }
        }
        __syncthreads();
    }

    // ---- epilogue: store unnormalized partials, both halves ----
    float* po = &g_po[split][0];
    #pragma unroll
    for (int h = 0; h < 2; h++) {
        float (*o)[4] = (h == 0) ? o0 : o1;
        int r0 = q0 + w * 32 + h * 16 + g;
        #pragma unroll
        for (int n = 0; n < 5; n++) {
            int col = head * DH + n * 8 + 2 * t;
            *(float2*)&po[r0 * D_MODEL + col] = make_float2(o[n][0], o[n][1]);
            *(float2*)&po[(r0 + 8) * D_MODEL + col] = make_float2(o[n][2], o[n][3]);
        }
        if (t == 0) {
            g_pl[split][head * S_LEN + r0] = o[5][0];
            g_pl[split][head * S_LEN + r0 + 8] = o[5][2];
        }
    }
}

// ============================================================
// Combine (vectorized): ctx = (sum O_s)/(sum l_s) -> (hi,lo) fp16
// ============================================================
__global__ void __launch_bounds__(256) attn_combine()
{
    int j = blockIdx.x * 256 + threadIdx.x;   // pair index over [S_LEN][DU32/2]
    if (j >= S_LEN * (DU32 / 2)) return;
    int row = j / (DU32 / 2);
    int cup = j % (DU32 / 2);
    int head = cup / (DH / 4);   // 10 pairs per head

    float l = 0.f, v0 = 0.f, v1 = 0.f, v2 = 0.f, v3 = 0.f;
    #pragma unroll
    for (int s = 0; s < NSPLIT; s++) {
        l += g_pl[s][head * S_LEN + row];
        float4 a = *(const float4*)&g_po[s][j * 4];
        v0 += a.x; v1 += a.y; v2 += a.z; v3 += a.w;
    }
    float inv = 1.f / l;
    v0 *= inv; v1 *= inv; v2 *= inv; v3 *= inv;

    __half2 h0 = __floats2half2_rn(v0, v1);
    __half2 h1 = __floats2half2_rn(v2, v3);
    __half2 e0 = __floats2half2_rn(v0 - __half2float(__low2half(h0)),
                                   v1 - __half2float(__high2half(h0)));
    __half2 e1 = __floats2half2_rn(v2 - __half2float(__low2half(h1)),
                                   v3 - __half2float(__high2half(h1)));
    ((uint2*)g_ch)[j] = make_uint2(*(uint32_t*)&h0, *(uint32_t*)&h1);
    ((uint2*)g_cl)[j] = make_uint2(*(uint32_t*)&e0, *(uint32_t*)&e1);
}

// ============================================================
extern "C" void kernel_launch(void* const* d_in, const int* in_sizes, int n_in,
                              void* d_out, int out_size)
{
    const float* x  = (const float*)d_in[0];
    const float* Wq = (const float*)d_in[1];
    const float* Wk = (const float*)d_in[2];
    const float* Wv = (const float*)d_in[3];
    const float* Wo = (const float*)d_in[4];
    const float* bo = (const float*)d_in[5];
    float* out = (float*)d_out;

    convert_w_kernel<<<dim3((D_MODEL * D_MODEL + 255) / 256, 1, 4), 256>>>(Wq, Wk, Wv, Wo);

    gemm_qkv_h<<<dim3(S_LEN / 64, D_MODEL / 64), 128>>>(x);
    attn_kernel<<<dim3(S_LEN / BR, NH, NSPLIT), 128>>>();
    attn_combine<<<(S_LEN * (DU32 / 2) + 255) / 256, 256>>>();
    gemm_out_h<<<dim3(S_LEN / 64, D_MODEL / 64), 128>>>(bo, out);
}

// round 17
// speedup vs baseline: 1.1434x; 1.0233x over previous
#include <cuda_runtime.h>
#include <cuda_fp16.h>
#include <stdint.h>
#include <math.h>

#define S_LEN 4096
#define D_MODEL 320
#define DU32 160          // D_MODEL halves as u32 (== float2 per row)
#define NH 8
#define DH 40
#define BR 128            // q rows per CTA (4 warps x m32)
#define BC 64
#define NSPLIT 4
#define KRANGE (S_LEN / NSPLIT)
#define LOG2E 1.4426950408889634f

// -------- scratch (device globals: allocation-free) --------
__device__ __align__(16) __half g_qh[S_LEN * D_MODEL];
__device__ __align__(16) __half g_kh[S_LEN * D_MODEL];
__device__ __align__(16) __half g_vh[S_LEN * D_MODEL];
__device__ __align__(16) __half g_ch[S_LEN * D_MODEL];
__device__ __align__(16) __half g_cl[S_LEN * D_MODEL];
__device__ float  g_po[NSPLIT][S_LEN * D_MODEL];   // unnormalized O partials
__device__ float  g_pl[NSPLIT][NH * S_LEN];        // l partials

// ============================================================
// HMMA / async helpers
// ============================================================
__device__ __forceinline__ void mma_f16(float c[4], uint32_t a0, uint32_t a1,
                                        uint32_t a2, uint32_t a3,
                                        uint32_t b0, uint32_t b1)
{
    asm volatile(
        "mma.sync.aligned.m16n8k16.row.col.f32.f16.f16.f32 "
        "{%0,%1,%2,%3}, {%4,%5,%6,%7}, {%8,%9}, {%0,%1,%2,%3};\n"
        : "+f"(c[0]), "+f"(c[1]), "+f"(c[2]), "+f"(c[3])
        : "r"(a0), "r"(a1), "r"(a2), "r"(a3), "r"(b0), "r"(b1));
}

__device__ __forceinline__ void ldmatrix_x4(uint32_t& r0, uint32_t& r1,
                                            uint32_t& r2, uint32_t& r3, uint32_t addr)
{
    asm volatile("ldmatrix.sync.aligned.m8n8.x4.shared.b16 {%0,%1,%2,%3}, [%4];"
                 : "=r"(r0), "=r"(r1), "=r"(r2), "=r"(r3) : "r"(addr));
}

__device__ __forceinline__ void ldmatrix_x4_trans(uint32_t& r0, uint32_t& r1,
                                                  uint32_t& r2, uint32_t& r3, uint32_t addr)
{
    asm volatile("ldmatrix.sync.aligned.m8n8.x4.trans.shared.b16 {%0,%1,%2,%3}, [%4];"
                 : "=r"(r0), "=r"(r1), "=r"(r2), "=r"(r3) : "r"(addr));
}

__device__ __forceinline__ uint32_t exp2_f16x2(float s0, float s1)
{
    __half2 h = __floats2half2_rn(s0, s1);
    uint32_t r;
    asm volatile("ex2.approx.f16x2 %0, %1;" : "=r"(r) : "r"(*(uint32_t*)&h));
    return r;
}

#define CP_ASYNC16(dst, src) \
    asm volatile("cp.async.cg.shared.global [%0], [%1], 16;\n" :: "r"(dst), "l"(src))
#define CP_COMMIT() asm volatile("cp.async.commit_group;\n" ::: "memory")
#define CP_WAIT1() asm volatile("cp.async.wait_group 1;\n" ::: "memory")
#define CP_WAIT0() asm volatile("cp.async.wait_group 0;\n" ::: "memory")

// ============================================================
// FUSED QKV GEMM: {Q,K,V} = x @ {Wq,Wk,Wv}^T in ONE kernel.
// x AND W read as fp32, converted to fp16 in-kernel (no
// separate convert kernel). x split hi/lo (2-term compensated).
// BM=64 (4 warps x m16), BN=64, k-step 16, 128 threads.
// ============================================================
#define PA_STR 12
#define GTILE (64 * PA_STR)          // u32 per logical tile
#define GSTAGE_B (GTILE * 4)         // bytes per smem stage (single tile)

__global__ void __launch_bounds__(128) gemm_qkv_h(
    const float* __restrict__ x,
    const float* __restrict__ Wq,
    const float* __restrict__ Wk,
    const float* __restrict__ Wv)
{
    __shared__ __align__(16) uint32_t Ah[2][GTILE];
    __shared__ __align__(16) uint32_t Al[2][GTILE];
    __shared__ __align__(16) uint32_t Wh[2][3][GTILE];

    const float2* __restrict__ x2 = (const float2*)x;
    const float2* __restrict__ wp[3] = {
        (const float2*)Wq, (const float2*)Wk, (const float2*)Wv };
    const float qscale = rsqrtf((float)DH) * LOG2E;

    const int tid = threadIdx.x;
    const int w = tid >> 5;
    const int lane = tid & 31;
    const int g = lane >> 2;
    const int t = lane & 3;
    const int m0 = blockIdx.x * 64;
    const int n0 = blockIdx.y * 64;
    const int rr = tid >> 3;
    const int cc = tid & 7;

    const int quad = lane >> 3;
    const int qi = lane & 7;
    const uint32_t ah_sh = (uint32_t)__cvta_generic_to_shared(&Ah[0][0]);
    const uint32_t al_sh = (uint32_t)__cvta_generic_to_shared(&Al[0][0]);
    const uint32_t wh_sh = (uint32_t)__cvta_generic_to_shared(&Wh[0][0][0]);
    const uint32_t a_off = (((w * 16 + (quad & 1) * 8 + qi) * PA_STR) + (quad >> 1) * 4) * 4;
    const uint32_t w_off = ((((quad >> 1) * 8 + qi) * PA_STR) + (quad & 1) * 4) * 4;

    float acc[3][8][4] = {};
    float2 ax[4];
    float2 wx[3][4];

    // preload kb=0
    #pragma unroll
    for (int it = 0; it < 4; it++) {
        int row = rr + it * 16;
        ax[it] = x2[(m0 + row) * DU32 + cc];
        #pragma unroll
        for (int z = 0; z < 3; z++)
            wx[z][it] = wp[z][(n0 + row) * DU32 + cc];
    }

    for (int kb = 0; kb < 20; kb++) {
        const int s = kb & 1;
        // store stage s (convert in-flight)
        #pragma unroll
        for (int it = 0; it < 4; it++) {
            int row = rr + it * 16;
            float2 v = ax[it];
            __half2 h = __floats2half2_rn(v.x, v.y);
            __half2 l = __floats2half2_rn(v.x - __half2float(__low2half(h)),
                                          v.y - __half2float(__high2half(h)));
            Ah[s][row * PA_STR + cc] = *(uint32_t*)&h;
            Al[s][row * PA_STR + cc] = *(uint32_t*)&l;
            #pragma unroll
            for (int z = 0; z < 3; z++) {
                float sc = (z == 0) ? qscale : 1.0f;
                __half2 hw = __floats2half2_rn(wx[z][it].x * sc, wx[z][it].y * sc);
                Wh[s][z][row * PA_STR + cc] = *(uint32_t*)&hw;
            }
        }
        __syncthreads();

        // prefetch kb+1 (overlaps compute)
        if (kb < 19) {
            #pragma unroll
            for (int it = 0; it < 4; it++) {
                int row = rr + it * 16;
                ax[it] = x2[(m0 + row) * DU32 + (kb + 1) * 8 + cc];
                #pragma unroll
                for (int z = 0; z < 3; z++)
                    wx[z][it] = wp[z][(n0 + row) * DU32 + (kb + 1) * 8 + cc];
            }
        }

        uint32_t a0, a1, a2, a3, l0, l1, l2, l3;
        ldmatrix_x4(a0, a1, a2, a3, ah_sh + s * GSTAGE_B + a_off);
        ldmatrix_x4(l0, l1, l2, l3, al_sh + s * GSTAGE_B + a_off);

        const uint32_t wsb = wh_sh + s * (3 * GSTAGE_B) + w_off;
        #pragma unroll
        for (int z = 0; z < 3; z++) {
            #pragma unroll
            for (int ap = 0; ap < 4; ap++) {
                uint32_t b0, b1, b2, b3;
                ldmatrix_x4(b0, b1, b2, b3,
                            wsb + z * GSTAGE_B + ap * (16 * PA_STR * 4));
                mma_f16(acc[z][2 * ap],     a0, a1, a2, a3, b0, b1);
                mma_f16(acc[z][2 * ap],     l0, l1, l2, l3, b0, b1);
                mma_f16(acc[z][2 * ap + 1], a0, a1, a2, a3, b2, b3);
                mma_f16(acc[z][2 * ap + 1], l0, l1, l2, l3, b2, b3);
            }
        }
    }

    int row = m0 + w * 16 + g;
    #pragma unroll
    for (int z = 0; z < 3; z++) {
        uint32_t* __restrict__ out32 =
            (uint32_t*)((z == 0) ? g_qh : (z == 1) ? g_kh : g_vh);
        #pragma unroll
        for (int a = 0; a < 8; a++) {
            int colu = (n0 >> 1) + 4 * a + t;
            __half2 v0 = __floats2half2_rn(acc[z][a][0], acc[z][a][1]);
            __half2 v1 = __floats2half2_rn(acc[z][a][2], acc[z][a][3]);
            out32[row * DU32 + colu] = *(uint32_t*)&v0;
            out32[(row + 8) * DU32 + colu] = *(uint32_t*)&v1;
        }
    }
}

// ============================================================
// Output projection: out = ctx @ Wo^T + bo. Wo converted
// fp32->fp16 in-kernel.
// ============================================================
__global__ void __launch_bounds__(128) gemm_out_h(
    const float* __restrict__ Wo,
    const float* __restrict__ bo, float* __restrict__ out)
{
    __shared__ __align__(16) uint32_t Ah[2][GTILE];
    __shared__ __align__(16) uint32_t Al[2][GTILE];
    __shared__ __align__(16) uint32_t Wh[2][GTILE];

    const uint32_t* __restrict__ xh32 = (const uint32_t*)g_ch;
    const uint32_t* __restrict__ xl32 = (const uint32_t*)g_cl;
    const float2* __restrict__ w2 = (const float2*)Wo;

    const int tid = threadIdx.x;
    const int w = tid >> 5;
    const int lane = tid & 31;
    const int g = lane >> 2;
    const int t = lane & 3;
    const int m0 = blockIdx.x * 64;
    const int n0 = blockIdx.y * 64;
    const int rr = tid >> 3;
    const int cc = tid & 7;

    const int quad = lane >> 3;
    const int qi = lane & 7;
    const uint32_t ah_sh = (uint32_t)__cvta_generic_to_shared(&Ah[0][0]);
    const uint32_t al_sh = (uint32_t)__cvta_generic_to_shared(&Al[0][0]);
    const uint32_t wh_sh = (uint32_t)__cvta_generic_to_shared(&Wh[0][0]);
    const uint32_t a_off = (((w * 16 + (quad & 1) * 8 + qi) * PA_STR) + (quad >> 1) * 4) * 4;
    const uint32_t w_off = ((((quad >> 1) * 8 + qi) * PA_STR) + (quad & 1) * 4) * 4;

    float acc[8][4] = {};
    uint32_t av[4], lv[4];
    float2 wx[4];

    #pragma unroll
    for (int it = 0; it < 4; it++) {
        int row = rr + it * 16;
        av[it] = xh32[(m0 + row) * DU32 + cc];
        lv[it] = xl32[(m0 + row) * DU32 + cc];
        wx[it] = w2[(n0 + row) * DU32 + cc];
    }

    for (int kb = 0; kb < 20; kb++) {
        const int s = kb & 1;
        #pragma unroll
        for (int it = 0; it < 4; it++) {
            int row = rr + it * 16;
            Ah[s][row * PA_STR + cc] = av[it];
            Al[s][row * PA_STR + cc] = lv[it];
            __half2 hw = __floats2half2_rn(wx[it].x, wx[it].y);
            Wh[s][row * PA_STR + cc] = *(uint32_t*)&hw;
        }
        __syncthreads();

        if (kb < 19) {
            #pragma unroll
            for (int it = 0; it < 4; it++) {
                int row = rr + it * 16;
                av[it] = xh32[(m0 + row) * DU32 + (kb + 1) * 8 + cc];
                lv[it] = xl32[(m0 + row) * DU32 + (kb + 1) * 8 + cc];
                wx[it] = w2[(n0 + row) * DU32 + (kb + 1) * 8 + cc];
            }
        }

        const uint32_t sb = s * GSTAGE_B;
        uint32_t a0, a1, a2, a3, l0, l1, l2, l3;
        ldmatrix_x4(a0, a1, a2, a3, ah_sh + sb + a_off);
        ldmatrix_x4(l0, l1, l2, l3, al_sh + sb + a_off);

        #pragma unroll
        for (int ap = 0; ap < 4; ap++) {
            uint32_t b0, b1, b2, b3;
            ldmatrix_x4(b0, b1, b2, b3, wh_sh + sb + w_off + ap * (16 * PA_STR * 4));
            mma_f16(acc[2 * ap],     a0, a1, a2, a3, b0, b1);
            mma_f16(acc[2 * ap],     l0, l1, l2, l3, b0, b1);
            mma_f16(acc[2 * ap + 1], a0, a1, a2, a3, b2, b3);
            mma_f16(acc[2 * ap + 1], l0, l1, l2, l3, b2, b3);
        }
    }

    int row = m0 + w * 16 + g;
    #pragma unroll
    for (int a = 0; a < 8; a++) {
        int col = n0 + 8 * a + 2 * t;
        float b0v = bo[col], b1v = bo[col + 1];
        float2 v0 = make_float2(acc[a][0] + b0v, acc[a][1] + b1v);
        float2 v1 = make_float2(acc[a][2] + b0v, acc[a][3] + b1v);
        *(float2*)&out[row * D_MODEL + col] = v0;
        *(float2*)&out[(row + 8) * D_MODEL + col] = v1;
    }
}

// ============================================================
// Flash attention (known-good R14). Split-K x4.
// CTA = 128 q x 1 head x 1024 keys. 4 warps m32 x n64.
// Qs smem, 2-stage cp.async, K via ldmatrix.x4, V via x4.trans,
// fixed-base exp2 softmax, register P, l via ones-column.
// ============================================================
#define QS_STRIDE 28
#define KS_STRIDE 28
#define VS_STRIDE 28
#define KV_TILE (64 * 28)
#define KV_TILE_B (KV_TILE * 4)

__global__ void __launch_bounds__(128, 4) attn_kernel()
{
    __shared__ __align__(16) uint32_t Qs[128 * QS_STRIDE];
    __shared__ __align__(16) uint32_t Ks[2 * KV_TILE];
    __shared__ __align__(16) uint32_t Vs[2 * KV_TILE];

    const uint32_t* __restrict__ q32 = (const uint32_t*)g_qh;
    const uint32_t* __restrict__ k32 = (const uint32_t*)g_kh;
    const uint32_t* __restrict__ v32 = (const uint32_t*)g_vh;

    const int tid = threadIdx.x;
    const int w = tid >> 5;
    const int lane = tid & 31;
    const int g = lane >> 2;
    const int t = lane & 3;
    const int head = blockIdx.y;
    const int split = blockIdx.z;
    const int q0 = blockIdx.x * BR;
    const int hoff = head * (DH / 2);
    const int kb0 = split * KRANGE;

    const uint32_t ks_sh = (uint32_t)__cvta_generic_to_shared(&Ks[0]);
    const uint32_t vs_sh = (uint32_t)__cvta_generic_to_shared(&Vs[0]);

    // ---- prologue: K pad cols zero; V col 20 = ones, 21..23 zero ----
    for (int idx = tid; idx < 2 * 64 * 4; idx += 128) {
        int st = idx >> 8;
        int rem = idx & 255;
        int r = rem >> 2, c = 20 + (rem & 3);
        Ks[st * KV_TILE + r * KS_STRIDE + c] = 0u;
        Vs[st * KV_TILE + r * VS_STRIDE + c] = (c == 20) ? 0x3C003C00u : 0u;
    }

    // ---- load Q tile: 128 rows x 24 u32 ----
    for (int idx = tid; idx < 128 * 24; idx += 128) {
        int r = idx / 24, c = idx % 24;
        Qs[r * QS_STRIDE + c] = (c < 20) ? q32[(q0 + r) * DU32 + hoff + c] : 0u;
    }

    // ---- hoisted cp.async addressing ----
    const uint32_t* srcPtr[5];
    uint32_t dstOff[5];
    #pragma unroll
    for (int j = 0; j < 5; j++) {
        int idx = tid + j * 128;
        int i2 = idx;
        bool isV = i2 >= 320;
        if (isV) i2 -= 320;
        int r = i2 / 5, c = i2 % 5;
        srcPtr[j] = (isV ? v32 : k32) + (kb0 + r) * DU32 + hoff + c * 4;
        dstOff[j] = (isV ? vs_sh : ks_sh) + (r * KS_STRIDE + c * 4) * 4;
    }

    #pragma unroll
    for (int j = 0; j < 5; j++) {
        CP_ASYNC16(dstOff[j], srcPtr[j]);
        srcPtr[j] += BC * DU32;
    }
    CP_COMMIT();
    __syncthreads();

    // ---- Q A-fragments register-resident: 2 m-halves x 3 k-steps ----
    uint32_t qa[2][3][4];
    #pragma unroll
    for (int h = 0; h < 2; h++) {
        int r0 = (w * 32 + h * 16 + g) * QS_STRIDE;
        int r1 = r0 + 8 * QS_STRIDE;
        #pragma unroll
        for (int ks = 0; ks < 3; ks++) {
            qa[h][ks][0] = Qs[r0 + ks * 8 + t];
            qa[h][ks][1] = Qs[r1 + ks * 8 + t];
            qa[h][ks][2] = Qs[r0 + ks * 8 + t + 4];
            qa[h][ks][3] = Qs[r1 + ks * 8 + t + 4];
        }
    }

    // ---- per-lane ldmatrix base addresses ----
    const int kq = lane >> 3;
    const int ki = lane & 7;
    const uint32_t kbase = ks_sh +
        ((((kq >> 1) * 8 + ki) * KS_STRIDE) + (kq & 1) * 4) * 4;
    const uint32_t vbase = vs_sh + (lane & 15) * (VS_STRIDE * 4) + (lane >> 4) * 16;

    float o0[6][4] = {};   // m-half 0: atoms 0..4 cols, atom 5 = l
    float o1[6][4] = {};   // m-half 1

    const int NIT = KRANGE / BC;
    for (int iter = 0; iter < NIT; iter++) {
        const int st = iter & 1;

        if (iter + 1 < NIT) {
            const uint32_t so = ((iter + 1) & 1) * KV_TILE_B;
            #pragma unroll
            for (int j = 0; j < 5; j++) {
                CP_ASYNC16(dstOff[j] + so, srcPtr[j]);
                srcPtr[j] += BC * DU32;
            }
            CP_COMMIT();
            CP_WAIT1();
        } else {
            CP_WAIT0();
        }
        __syncthreads();

        const uint32_t kst = kbase + st * KV_TILE_B;
        const uint32_t vst = vbase + st * KV_TILE_B;

        // ---- S = Q K^T per atom-pair; P = 2^S into registers ----
        uint32_t pa01[8], pa23[8];   // P for m-half 0
        uint32_t pb01[8], pb23[8];   // P for m-half 1
        #pragma unroll
        for (int ap = 0; ap < 4; ap++) {
            float sA0[4] = {}, sA1[4] = {}, sB0[4] = {}, sB1[4] = {};
            #pragma unroll
            for (int ks = 0; ks < 3; ks++) {
                uint32_t b0, b1, b2, b3;
                ldmatrix_x4(b0, b1, b2, b3,
                            kst + ap * (16 * KS_STRIDE * 4) + ks * 32);
                mma_f16(sA0, qa[0][ks][0], qa[0][ks][1], qa[0][ks][2], qa[0][ks][3], b0, b1);
                mma_f16(sA1, qa[1][ks][0], qa[1][ks][1], qa[1][ks][2], qa[1][ks][3], b0, b1);
                mma_f16(sB0, qa[0][ks][0], qa[0][ks][1], qa[0][ks][2], qa[0][ks][3], b2, b3);
                mma_f16(sB1, qa[1][ks][0], qa[1][ks][1], qa[1][ks][2], qa[1][ks][3], b2, b3);
            }
            int a0i = 2 * ap, a1i = 2 * ap + 1;
            pa01[a0i] = exp2_f16x2(sA0[0], sA0[1]);
            pa23[a0i] = exp2_f16x2(sA0[2], sA0[3]);
            pb01[a0i] = exp2_f16x2(sA1[0], sA1[1]);
            pb23[a0i] = exp2_f16x2(sA1[2], sA1[3]);
            pa01[a1i] = exp2_f16x2(sB0[0], sB0[1]);
            pa23[a1i] = exp2_f16x2(sB0[2], sB0[3]);
            pb01[a1i] = exp2_f16x2(sB1[0], sB1[1]);
            pb23[a1i] = exp2_f16x2(sB1[2], sB1[3]);
        }

        // ---- O += P @ [V | 1]: x4.trans loads 2 n-atoms per instr ----
        #pragma unroll
        for (int ks = 0; ks < 4; ks++) {
            uint32_t vk = vst + ks * (16 * VS_STRIDE * 4);
            uint32_t a0 = pa01[2 * ks], a1 = pa23[2 * ks];
            uint32_t a2 = pa01[2 * ks + 1], a3 = pa23[2 * ks + 1];
            uint32_t c0 = pb01[2 * ks], c1 = pb23[2 * ks];
            uint32_t c2 = pb01[2 * ks + 1], c3 = pb23[2 * ks + 1];
            #pragma unroll
            for (int np = 0; np < 3; np++) {
                uint32_t b0, b1, b2, b3;
                ldmatrix_x4_trans(b0, b1, b2, b3, vk + np * 32);
                mma_f16(o0[2 * np],     a0, a1, a2, a3, b0, b1);
                mma_f16(o1[2 * np],     c0, c1, c2, c3, b0, b1);
                mma_f16(o0[2 * np + 1], a0, a1, a2, a3, b2, b3);
                mma_f16(o1[2 * np + 1], c0, c1, c2, c3, b2, b3);
            }
        }
        __syncthreads();
    }

    // ---- epilogue: store unnormalized partials, both halves ----
    float* po = &g_po[split][0];
    #pragma unroll
    for (int h = 0; h < 2; h++) {
        float (*o)[4] = (h == 0) ? o0 : o1;
        int r0 = q0 + w * 32 + h * 16 + g;
        #pragma unroll
        for (int n = 0; n < 5; n++) {
            int col = head * DH + n * 8 + 2 * t;
            *(float2*)&po[r0 * D_MODEL + col] = make_float2(o[n][0], o[n][1]);
            *(float2*)&po[(r0 + 8) * D_MODEL + col] = make_float2(o[n][2], o[n][3]);
        }
        if (t == 0) {
            g_pl[split][head * S_LEN + r0] = o[5][0];
            g_pl[split][head * S_LEN + r0 + 8] = o[5][2];
        }
    }
}

// ============================================================
// Combine (vectorized): ctx = (sum O_s)/(sum l_s) -> (hi,lo) fp16
// ============================================================
__global__ void __launch_bounds__(256) attn_combine()
{
    int j = blockIdx.x * 256 + threadIdx.x;   // pair index over [S_LEN][DU32/2]
    if (j >= S_LEN * (DU32 / 2)) return;
    int row = j / (DU32 / 2);
    int cup = j % (DU32 / 2);
    int head = cup / (DH / 4);   // 10 pairs per head

    float l = 0.f, v0 = 0.f, v1 = 0.f, v2 = 0.f, v3 = 0.f;
    #pragma unroll
    for (int s = 0; s < NSPLIT; s++) {
        l += g_pl[s][head * S_LEN + row];
        float4 a = *(const float4*)&g_po[s][j * 4];
        v0 += a.x; v1 += a.y; v2 += a.z; v3 += a.w;
    }
    float inv = 1.f / l;
    v0 *= inv; v1 *= inv; v2 *= inv; v3 *= inv;

    __half2 h0 = __floats2half2_rn(v0, v1);
    __half2 h1 = __floats2half2_rn(v2, v3);
    __half2 e0 = __floats2half2_rn(v0 - __half2float(__low2half(h0)),
                                   v1 - __half2float(__high2half(h0)));
    __half2 e1 = __floats2half2_rn(v2 - __half2float(__low2half(h1)),
                                   v3 - __half2float(__high2half(h1)));
    ((uint2*)g_ch)[j] = make_uint2(*(uint32_t*)&h0, *(uint32_t*)&h1);
    ((uint2*)g_cl)[j] = make_uint2(*(uint32_t*)&e0, *(uint32_t*)&e1);
}

// ============================================================
extern "C" void kernel_launch(void* const* d_in, const int* in_sizes, int n_in,
                              void* d_out, int out_size)
{
    const float* x  = (const float*)d_in[0];
    const float* Wq = (const float*)d_in[1];
    const float* Wk = (const float*)d_in[2];
    const float* Wv = (const float*)d_in[3];
    const float* Wo = (const float*)d_in[4];
    const float* bo = (const float*)d_in[5];
    float* out = (float*)d_out;

    gemm_qkv_h<<<dim3(S_LEN / 64, D_MODEL / 64), 128>>>(x, Wq, Wk, Wv);
    attn_kernel<<<dim3(S_LEN / BR, NH, NSPLIT), 128>>>();
    attn_combine<<<(S_LEN * (DU32 / 2) + 255) / 256, 256>>>();
    gemm_out_h<<<dim3(S_LEN / 64, D_MODEL / 64), 128>>>(Wo, bo, out);
}